// round 1
// baseline (speedup 1.0000x reference)
#include <cuda_runtime.h>
#include <math.h>

// ---------------------------------------------------------------------------
// Problem constants
//   B=32, T=512, N=4, E=16, NI=16, EI=8, HN=HE=128, MH=256, C=8
//   M_node = B*T*N = 65536, M_edge = B*T*E = 262144
// ---------------------------------------------------------------------------

#define SPB 5   // sequences per LSTM block
#define LSTM_SMEM_FLOATS (96*512 + 2*SPB*128 + SPB*512)
#define LSTM_SMEM_BYTES  (LSTM_SMEM_FLOATS * 4)

// Static scratch (allocation-free rule: __device__ globals)
__device__ float g_nA[65536 * 128];
__device__ float g_nB[65536 * 128];
__device__ float g_eA[262144 * 128];
__device__ float g_eB[262144 * 128];
__device__ float g_xzn[65536 * 512];
__device__ float g_xze[134217728];   // 262144 * 512
__device__ float g_c1[67108864];     // 262144 * 256

__device__ __forceinline__ float sigmf(float x) {
    return 1.0f / (1.0f + __expf(-x));
}
__device__ __forceinline__ float tanhfast(float x) {
    // 1 - 2/(e^{2x}+1); saturates cleanly at +-1, no NaNs
    return 1.0f - 2.0f / (__expf(2.0f * x) + 1.0f);
}

// ---------------------------------------------------------------------------
// Generic SGEMM: C[M,N] = act(A[M,K] @ B[K,N] + bias)
// Requirements (all satisfied here): M % 128 == 0, N % 128 == 0, K % 8 == 0.
// BM=BN=128, BK=8, 256 threads, 8x8 microtile.
// ---------------------------------------------------------------------------
template <int RELU, int HASBIAS>
__global__ __launch_bounds__(256) void sgemm_k(
    const float* __restrict__ A, const float* __restrict__ B,
    const float* __restrict__ bias, float* __restrict__ C,
    int M, int N, int K)
{
    __shared__ float As[8][128];
    __shared__ float Bs[8][128];
    const int tid  = threadIdx.x;
    const int bm   = blockIdx.y * 128;
    const int bn   = blockIdx.x * 128;
    const int arow = tid >> 1;
    const int acol = (tid & 1) * 4;
    const int brow = tid >> 5;
    const int bcol = (tid & 31) * 4;
    const int tx   = (tid & 15) * 8;
    const int ty   = (tid >> 4) * 8;

    const float* Ab = A + (size_t)(bm + arow) * K + acol;
    const float* Bb = B + (size_t)brow * N + bn + bcol;

    float acc[8][8];
#pragma unroll
    for (int i = 0; i < 8; i++)
#pragma unroll
        for (int j = 0; j < 8; j++) acc[i][j] = 0.f;

    for (int k0 = 0; k0 < K; k0 += 8) {
        float4 av = *(const float4*)(Ab + k0);
        float4 bv = *(const float4*)(Bb + (size_t)k0 * N);
        As[acol + 0][arow] = av.x;
        As[acol + 1][arow] = av.y;
        As[acol + 2][arow] = av.z;
        As[acol + 3][arow] = av.w;
        *(float4*)&Bs[brow][bcol] = bv;
        __syncthreads();
#pragma unroll
        for (int kk = 0; kk < 8; kk++) {
            float ar[8], br[8];
            *(float4*)&ar[0] = *(const float4*)&As[kk][ty];
            *(float4*)&ar[4] = *(const float4*)&As[kk][ty + 4];
            *(float4*)&br[0] = *(const float4*)&Bs[kk][tx];
            *(float4*)&br[4] = *(const float4*)&Bs[kk][tx + 4];
#pragma unroll
            for (int i = 0; i < 8; i++)
#pragma unroll
                for (int j = 0; j < 8; j++)
                    acc[i][j] += ar[i] * br[j];
        }
        __syncthreads();
    }

    float bv_[8];
    if (HASBIAS) {
        *(float4*)&bv_[0] = *(const float4*)&bias[bn + tx];
        *(float4*)&bv_[4] = *(const float4*)&bias[bn + tx + 4];
    }
#pragma unroll
    for (int i = 0; i < 8; i++) {
        float* Crow = C + (size_t)(bm + ty + i) * N + bn + tx;
        float v[8];
#pragma unroll
        for (int j = 0; j < 8; j++) {
            v[j] = acc[i][j];
            if (HASBIAS) v[j] += bv_[j];
            if (RELU)    v[j] = fmaxf(v[j], 0.f);
        }
        *(float4*)(Crow)     = make_float4(v[0], v[1], v[2], v[3]);
        *(float4*)(Crow + 4) = make_float4(v[4], v[5], v[6], v[7]);
    }
}

// ---------------------------------------------------------------------------
// Classifier GEMM with fused gather:
//   feats[row, k] = k<128 ? hn[bt*4 + e/4][k] : k<256 ? hn[bt*4 + e%4][k-128]
//                                             : he[row][k-256]
//   C = relu(feats @ Wc1 + bc1),  M=262144, K=384, N=256
// ---------------------------------------------------------------------------
__global__ __launch_bounds__(256) void sgemm_c1(
    const float* __restrict__ hn, const float* __restrict__ he,
    const float* __restrict__ Wc1, const float* __restrict__ bc1,
    float* __restrict__ C)
{
    const int N = 256, K = 384;
    __shared__ float As[8][128];
    __shared__ float Bs[8][128];
    const int tid  = threadIdx.x;
    const int bm   = blockIdx.y * 128;
    const int bn   = blockIdx.x * 128;
    const int arow = tid >> 1;
    const int acol = (tid & 1) * 4;
    const int brow = tid >> 5;
    const int bcol = (tid & 31) * 4;
    const int tx   = (tid & 15) * 8;
    const int ty   = (tid >> 4) * 8;

    const int row = bm + arow;
    const int bt  = row >> 4;
    const int e   = row & 15;
    const float* seg0 = hn + ((size_t)bt * 4 + (e >> 2)) * 128;  // src
    const float* seg1 = hn + ((size_t)bt * 4 + (e & 3)) * 128;   // dst
    const float* seg2 = he + (size_t)row * 128;

    const float* Bb = Wc1 + (size_t)brow * N + bn + bcol;

    float acc[8][8];
#pragma unroll
    for (int i = 0; i < 8; i++)
#pragma unroll
        for (int j = 0; j < 8; j++) acc[i][j] = 0.f;

    for (int k0 = 0; k0 < K; k0 += 8) {
        const float* sp = (k0 < 128) ? seg0 : ((k0 < 256) ? seg1 : seg2);
        float4 av = *(const float4*)(sp + (k0 & 127) + acol);
        float4 bv = *(const float4*)(Bb + (size_t)k0 * N);
        As[acol + 0][arow] = av.x;
        As[acol + 1][arow] = av.y;
        As[acol + 2][arow] = av.z;
        As[acol + 3][arow] = av.w;
        *(float4*)&Bs[brow][bcol] = bv;
        __syncthreads();
#pragma unroll
        for (int kk = 0; kk < 8; kk++) {
            float ar[8], br[8];
            *(float4*)&ar[0] = *(const float4*)&As[kk][ty];
            *(float4*)&ar[4] = *(const float4*)&As[kk][ty + 4];
            *(float4*)&br[0] = *(const float4*)&Bs[kk][tx];
            *(float4*)&br[4] = *(const float4*)&Bs[kk][tx + 4];
#pragma unroll
            for (int i = 0; i < 8; i++)
#pragma unroll
                for (int j = 0; j < 8; j++)
                    acc[i][j] += ar[i] * br[j];
        }
        __syncthreads();
    }

    float bv_[8];
    *(float4*)&bv_[0] = *(const float4*)&bc1[bn + tx];
    *(float4*)&bv_[4] = *(const float4*)&bc1[bn + tx + 4];
#pragma unroll
    for (int i = 0; i < 8; i++) {
        float* Crow = C + (size_t)(bm + ty + i) * N + bn + tx;
        float v[8];
#pragma unroll
        for (int j = 0; j < 8; j++)
            v[j] = fmaxf(acc[i][j] + bv_[j], 0.f);
        *(float4*)(Crow)     = make_float4(v[0], v[1], v[2], v[3]);
        *(float4*)(Crow + 4) = make_float4(v[4], v[5], v[6], v[7]);
    }
}

// ---------------------------------------------------------------------------
// Graph-conv mixing: out[bt,n,h] = relu((sum_j z[bt,j,h] + z[bt,n,h])/5 + b[h])
// (NORM_ADJ = (ones + eye)/5, N=4)
// ---------------------------------------------------------------------------
__global__ void adjmix_k(const float* __restrict__ z,
                         const float* __restrict__ bias,
                         float* __restrict__ out)
{
    int idx = blockIdx.x * 256 + threadIdx.x;   // < 16384*128
    int h  = idx & 127;
    int bt = idx >> 7;
    const float* p = z + (size_t)bt * 512 + h;
    float z0 = p[0], z1 = p[128], z2 = p[256], z3 = p[384];
    float s = z0 + z1 + z2 + z3;
    float b = bias[h];
    float* q = out + (size_t)bt * 512 + h;
    q[0]   = fmaxf((s + z0) * 0.2f + b, 0.f);
    q[128] = fmaxf((s + z1) * 0.2f + b, 0.f);
    q[256] = fmaxf((s + z2) * 0.2f + b, 0.f);
    q[384] = fmaxf((s + z3) * 0.2f + b, 0.f);
}

// ---------------------------------------------------------------------------
// Fused LSTM (node + edge in one launch).
// Blocks 0..25: node sequences (128 of them), blocks 26..128: edge (512).
// Each block owns SPB=5 sequences; Whh rows 0..95 in SMEM, rows 96..127 in
// registers (2 columns per thread). 129 blocks = one wave.
// ---------------------------------------------------------------------------
__global__ __launch_bounds__(256, 1) void lstm_kernel(
    const float* __restrict__ xz_n, const float* __restrict__ Whh_n, float* __restrict__ hn,
    const float* __restrict__ xz_e, const float* __restrict__ Whh_e, float* __restrict__ he)
{
    extern __shared__ float sm[];
    float* ws  = sm;                     // 96*512
    float* hsm = ws + 96 * 512;          // SPB*128
    float* csm = hsm + SPB * 128;        // SPB*128
    float* zsm = csm + SPB * 128;        // SPB*512

    const int tid  = threadIdx.x;
    const int col0 = tid;
    const int col1 = tid + 256;

    const float* Whh;
    const float* xz;
    float* out;
    int seq0, nseq;
    long xbase[SPB], obase[SPB];
    long xstep, ostep;

    if (blockIdx.x < 26) {
        Whh = Whh_n; xz = xz_n; out = hn;
        seq0 = blockIdx.x * SPB; nseq = 128;
        xstep = 4 * 512; ostep = 4 * 128;          // row stride per t is N=4
#pragma unroll
        for (int i = 0; i < SPB; i++) {
            int s = seq0 + i;
            int b = s >> 2, n = s & 3;
            long row = (long)b * 2048 + n;          // b*T*4 + n
            xbase[i] = row * 512;
            obase[i] = row * 128;
        }
    } else {
        Whh = Whh_e; xz = xz_e; out = he;
        seq0 = (blockIdx.x - 26) * SPB; nseq = 512;
        xstep = 16 * 512; ostep = 16 * 128;         // row stride per t is E=16
#pragma unroll
        for (int i = 0; i < SPB; i++) {
            int s = seq0 + i;
            int b = s >> 4, e = s & 15;
            long row = (long)b * 8192 + e;          // b*T*16 + e
            xbase[i] = row * 512;
            obase[i] = row * 128;
        }
    }

    // Load Whh rows 0..95 into SMEM (float4), rows 96..127 into registers.
    for (int idx = tid; idx < (96 * 512) / 4; idx += 256)
        ((float4*)ws)[idx] = ((const float4*)Whh)[idx];
    float wr0[32], wr1[32];
#pragma unroll
    for (int r = 0; r < 32; r++) {
        wr0[r] = Whh[(96 + r) * 512 + col0];
        wr1[r] = Whh[(96 + r) * 512 + col1];
    }
    for (int idx = tid; idx < SPB * 128; idx += 256) {
        hsm[idx] = 0.f;
        csm[idx] = 0.f;
    }
    __syncthreads();

    for (int t = 0; t < 512; t++) {
        // Hoist xz loads (DRAM latency hides under the k-loop below)
        float xv0[SPB], xv1[SPB];
#pragma unroll
        for (int i = 0; i < SPB; i++) {
            if (seq0 + i < nseq) {
                const float* p = xz + xbase[i] + (long)t * xstep;
                xv0[i] = p[col0];
                xv1[i] = p[col1];
            } else {
                xv0[i] = 0.f;
                xv1[i] = 0.f;
            }
        }

        float a0[SPB], a1[SPB];
#pragma unroll
        for (int i = 0; i < SPB; i++) { a0[i] = 0.f; a1[i] = 0.f; }

        // rows 0..95 from SMEM
#pragma unroll 2
        for (int k = 0; k < 96; k += 4) {
            float hk[SPB][4];
#pragma unroll
            for (int i = 0; i < SPB; i++)
                *(float4*)hk[i] = *(const float4*)(hsm + i * 128 + k);
#pragma unroll
            for (int u = 0; u < 4; u++) {
                float w0 = ws[(k + u) * 512 + col0];
                float w1 = ws[(k + u) * 512 + col1];
#pragma unroll
                for (int i = 0; i < SPB; i++) {
                    a0[i] += hk[i][u] * w0;
                    a1[i] += hk[i][u] * w1;
                }
            }
        }
        // rows 96..127 from registers
#pragma unroll
        for (int r4 = 0; r4 < 32; r4 += 4) {
            float hk[SPB][4];
#pragma unroll
            for (int i = 0; i < SPB; i++)
                *(float4*)hk[i] = *(const float4*)(hsm + i * 128 + 96 + r4);
#pragma unroll
            for (int u = 0; u < 4; u++) {
#pragma unroll
                for (int i = 0; i < SPB; i++) {
                    a0[i] += hk[i][u] * wr0[r4 + u];
                    a1[i] += hk[i][u] * wr1[r4 + u];
                }
            }
        }
#pragma unroll
        for (int i = 0; i < SPB; i++) {
            zsm[i * 512 + col0] = a0[i] + xv0[i];
            zsm[i * 512 + col1] = a1[i] + xv1[i];
        }
        __syncthreads();

        // gates + state update + output
        for (int q = tid; q < SPB * 128; q += 256) {
            int i = q >> 7, hh = q & 127;
            const float* zrow = zsm + i * 512;
            float zi = zrow[hh];
            float zf = zrow[128 + hh];
            float zg = zrow[256 + hh];
            float zo = zrow[384 + hh];
            float cn = sigmf(zf) * csm[q] + sigmf(zi) * tanhfast(zg);
            float hv = sigmf(zo) * tanhfast(cn);
            csm[q] = cn;
            hsm[q] = hv;
            if (seq0 + i < nseq)
                out[obase[i] + (long)t * ostep + hh] = hv;
        }
        __syncthreads();
    }
}

// ---------------------------------------------------------------------------
// Final projection: out[row, c] = c1[row,:256] @ Wc2[:,c] + bc2[c], C=8
// 32 rows per block, A tile staged in padded SMEM (conflict-free).
// ---------------------------------------------------------------------------
__global__ __launch_bounds__(256) void final_k(
    const float* __restrict__ A, const float* __restrict__ W,
    const float* __restrict__ bias, float* __restrict__ out)
{
    __shared__ float ws[2048];       // 256 x 8
    __shared__ float as[32 * 264];   // padded rows
    const int tid = threadIdx.x;
    for (int i = tid; i < 2048; i += 256) ws[i] = W[i];

    long row0 = (long)blockIdx.x * 32;
    const float4* Ap = (const float4*)(A + row0 * 256);
    for (int i = tid; i < 2048; i += 256) {
        int r  = i >> 6;    // 64 float4 per row
        int c4 = i & 63;
        *(float4*)(as + r * 264 + c4 * 4) = Ap[(long)r * 64 + c4];
    }
    __syncthreads();

    int r = tid >> 3, c = tid & 7;
    float acc = bias[c];
    const float* arp = as + r * 264;
#pragma unroll 8
    for (int k = 0; k < 256; k++)
        acc += arp[k] * ws[k * 8 + c];
    out[(row0 + r) * 8 + c] = acc;
}

// ---------------------------------------------------------------------------
// Launch
// ---------------------------------------------------------------------------
extern "C" void kernel_launch(void* const* d_in, const int* in_sizes, int n_in,
                              void* d_out, int out_size)
{
    const float* x_seq = (const float*)d_in[0];
    const float* ea    = (const float*)d_in[1];
    const float* Wn1   = (const float*)d_in[2];
    const float* bn1   = (const float*)d_in[3];
    const float* Wn2   = (const float*)d_in[4];
    const float* bn2   = (const float*)d_in[5];
    const float* We1   = (const float*)d_in[6];
    const float* be1   = (const float*)d_in[7];
    const float* We2   = (const float*)d_in[8];
    const float* be2   = (const float*)d_in[9];
    const float* Wg1   = (const float*)d_in[10];
    const float* bg1   = (const float*)d_in[11];
    const float* Wg2   = (const float*)d_in[12];
    const float* bg2   = (const float*)d_in[13];
    const float* Wef1  = (const float*)d_in[14];
    const float* bef1  = (const float*)d_in[15];
    const float* Wef2  = (const float*)d_in[16];
    const float* bef2  = (const float*)d_in[17];
    const float* Wih_n = (const float*)d_in[18];
    const float* Whh_n = (const float*)d_in[19];
    const float* b_n   = (const float*)d_in[20];
    const float* Wih_e = (const float*)d_in[21];
    const float* Whh_e = (const float*)d_in[22];
    const float* b_e   = (const float*)d_in[23];
    const float* Wc1   = (const float*)d_in[24];
    const float* bc1   = (const float*)d_in[25];
    const float* Wc2   = (const float*)d_in[26];
    const float* bc2   = (const float*)d_in[27];
    float* out = (float*)d_out;

    (void)in_sizes; (void)n_in; (void)out_size;

    cudaFuncSetAttribute(lstm_kernel,
                         cudaFuncAttributeMaxDynamicSharedMemorySize,
                         LSTM_SMEM_BYTES);

    float* nA = g_nA; float* nB = g_nB;
    float* eA = g_eA; float* eB = g_eB;

    // ---- node path: MLP + graph conv (M=65536) ----
    dim3 gn(1, 512);
    sgemm_k<1, 1><<<gn, 256>>>(x_seq, Wn1, bn1, nA, 65536, 128, 16);
    sgemm_k<1, 1><<<gn, 256>>>(nA, Wn2, bn2, nB, 65536, 128, 128);
    sgemm_k<0, 0><<<gn, 256>>>(nB, Wg1, nullptr, nA, 65536, 128, 128);
    adjmix_k<<<8192, 256>>>(nA, bg1, nB);
    sgemm_k<0, 0><<<gn, 256>>>(nB, Wg2, nullptr, nA, 65536, 128, 128);
    adjmix_k<<<8192, 256>>>(nA, bg2, nB);                 // x4 in nB
    sgemm_k<0, 1><<<dim3(4, 512), 256>>>(nB, Wih_n, b_n, g_xzn, 65536, 512, 128);

    // ---- edge path: MLPs (M=262144) ----
    dim3 ge(1, 2048);
    sgemm_k<1, 1><<<ge, 256>>>(ea, We1, be1, eA, 262144, 128, 8);
    sgemm_k<1, 1><<<ge, 256>>>(eA, We2, be2, eB, 262144, 128, 128);
    sgemm_k<1, 1><<<ge, 256>>>(eB, Wef1, bef1, eA, 262144, 128, 128);
    sgemm_k<1, 1><<<ge, 256>>>(eA, Wef2, bef2, eB, 262144, 128, 128);  // e4 in eB
    sgemm_k<0, 1><<<dim3(4, 2048), 256>>>(eB, Wih_e, b_e, g_xze, 262144, 512, 128);

    // ---- fused node+edge LSTM: hn -> nA, he -> eA ----
    lstm_kernel<<<129, 256, LSTM_SMEM_BYTES>>>(g_xzn, Whh_n, nA,
                                               g_xze, Whh_e, eA);

    // ---- classifier: fused gather + GEMM1, then GEMM2 ----
    sgemm_c1<<<dim3(2, 2048), 256>>>(nA, eA, Wc1, bc1, g_c1);
    final_k<<<8192, 256>>>(g_c1, Wc2, bc2, out);
}